// round 3
// baseline (speedup 1.0000x reference)
#include <cuda_runtime.h>
#include <cstdint>

#define N_NEURON 1024
#define N_PEPTIDE 16
#define BATCH 2048
#define STATE_ROW 18433   // 1024 + 1 + 1024 + 16384
#define PEP_OFF 2049      // 1024 + 1 + 1024
#define NEU_OFF 1025
#define DT_VAL (1.0f / 120.0f)

// Scratch for GEMM result (firing @ synapse): 2048 x 1024 fp32 = 8 MB
__device__ float g_syn[BATCH * N_NEURON];

// ---------------------------------------------------------------------------
// Kernel 1: firing = clip(-(relu(neuron)*abl + 0.01) * log1p(-noise), 0, 10)
// ---------------------------------------------------------------------------
__global__ void k_firing(const float* __restrict__ state,
                         const float* __restrict__ noise,
                         float* __restrict__ firing)
{
    int idx = blockIdx.x * blockDim.x + threadIdx.x;   // 0 .. 2048*1024-1
    int b = idx >> 10;
    int n = idx & 1023;
    const float* srow = state + (size_t)b * STATE_ROW;
    float abl = __ldg(srow + n);
    float nv  = __ldg(srow + NEU_OFF + n);
    float f = fmaxf(nv, 0.0f) * abl;
    f = -(f + 0.01f) * log1pf(-__ldg(noise + idx));
    f = fminf(fmaxf(f, 0.0f), 10.0f);
    firing[idx] = f;
}

// ---------------------------------------------------------------------------
// Kernel 2: SGEMM  C[M,N] = A[M,K] * B[K,N]   (fp32, 128x128x8 tiles)
// M = 2048 (batch), N = 1024, K = 1024. A,B,C row-major.
// ---------------------------------------------------------------------------
#define BM 128
#define BN 128
#define BK 8
#define TM 8
#define TN 8

__global__ __launch_bounds__(256, 1)
void k_sgemm(const float* __restrict__ A,
             const float* __restrict__ B,
             float* __restrict__ C)
{
    const int M = BATCH, N = N_NEURON, K = N_NEURON;
    __shared__ float As[BK][BM];
    __shared__ float Bs[BK][BN];

    int tid = threadIdx.x;
    int bx = blockIdx.x;   // tile along N
    int by = blockIdx.y;   // tile along M

    int aRow = tid >> 1;            // 0..127
    int aCol = (tid & 1) * 4;       // 0 or 4
    int bRow = tid >> 5;            // 0..7
    int bCol = (tid & 31) * 4;      // 0..124

    const float* Ab = A + (size_t)by * BM * K;
    const float* Bb = B + bx * BN;

    int trow = (tid >> 4) * TM;     // 0..120
    int tcol = (tid & 15) * TN;     // 0..120

    float acc[TM][TN];
    #pragma unroll
    for (int i = 0; i < TM; i++)
        #pragma unroll
        for (int j = 0; j < TN; j++)
            acc[i][j] = 0.0f;

    for (int k0 = 0; k0 < K; k0 += BK) {
        float4 a4 = *reinterpret_cast<const float4*>(Ab + (size_t)aRow * K + k0 + aCol);
        As[aCol + 0][aRow] = a4.x;
        As[aCol + 1][aRow] = a4.y;
        As[aCol + 2][aRow] = a4.z;
        As[aCol + 3][aRow] = a4.w;
        float4 b4 = *reinterpret_cast<const float4*>(Bb + (size_t)(k0 + bRow) * N + bCol);
        *reinterpret_cast<float4*>(&Bs[bRow][bCol]) = b4;
        __syncthreads();

        #pragma unroll
        for (int k = 0; k < BK; k++) {
            float ra[TM], rb[TN];
            #pragma unroll
            for (int i = 0; i < TM; i++) ra[i] = As[k][trow + i];
            #pragma unroll
            for (int j = 0; j < TN; j++) rb[j] = Bs[k][tcol + j];
            #pragma unroll
            for (int i = 0; i < TM; i++)
                #pragma unroll
                for (int j = 0; j < TN; j++)
                    acc[i][j] += ra[i] * rb[j];
        }
        __syncthreads();
    }

    #pragma unroll
    for (int i = 0; i < TM; i++) {
        int row = by * BM + trow + i;
        float* Crow = C + (size_t)row * N + bx * BN + tcol;
        *reinterpret_cast<float4*>(Crow)     = make_float4(acc[i][0], acc[i][1], acc[i][2], acc[i][3]);
        *reinterpret_cast<float4*>(Crow + 4) = make_float4(acc[i][4], acc[i][5], acc[i][6], acc[i][7]);
    }
}

// ---------------------------------------------------------------------------
// Kernel 3: peptide laplacian + update, neuron update, state_new assembly.
// One block per batch row; 1024 threads = one per neuron.
// Peptide grid (1024 x 16) staged in SMEM, rows padded to 20 floats
// (stride-20 scalar access is bank-conflict-free for the rolled neighbors).
// ---------------------------------------------------------------------------
#define PPAD 20
#define SMEM_BYTES (N_NEURON * PPAD * 4)

__global__ __launch_bounds__(1024, 1)
void k_update(const float* __restrict__ state,
              const float* __restrict__ u,
              const float* __restrict__ firing,
              const float* __restrict__ D,
              const float* __restrict__ prod_r,
              const float* __restrict__ decay_r,
              const float* __restrict__ action,
              const float* __restrict__ ndecay,
              const float* __restrict__ input_layer,
              float* __restrict__ out_state)
{
    extern __shared__ float sp[];             // 1024 * 20 floats
    __shared__ float sD[16], sP[16], sR[16], sA[16];

    int b = blockIdx.x;
    int n = threadIdx.x;

    if (n < 16) {
        sD[n] = fabsf(__ldg(D + n));
        sP[n] = fabsf(__ldg(prod_r + n));
        sR[n] = fabsf(__ldg(decay_r + n));
        sA[n] = __ldg(action + n);
    }

    const float* srow = state + (size_t)b * STATE_ROW;
    const float* pep  = srow + PEP_OFF;

    // Stage peptide grid into padded SMEM (coalesced global reads)
    #pragma unroll
    for (int e = n; e < N_NEURON * N_PEPTIDE; e += N_NEURON) {
        sp[(e >> 4) * PPAD + (e & 15)] = __ldg(pep + e);
    }
    __syncthreads();

    int i = n >> 5, j = n & 31;
    const float* c0 = sp + n * PPAD;
    const float* cu = sp + ((((i + 1)  & 31) << 5) | j) * PPAD;
    const float* cd = sp + ((((i + 31) & 31) << 5) | j) * PPAD;
    const float* cr = sp + (((i << 5) | ((j + 1)  & 31))) * PPAD;
    const float* cl = sp + (((i << 5) | ((j + 31) & 31))) * PPAD;

    float f   = __ldg(firing + (size_t)b * N_NEURON + n);
    float abl = __ldg(srow + n);
    float nm  = __ldg(srow + NEU_OFF + n) * abl;
    float pc2 = __ldg(srow + N_NEURON);

    float* orow = out_state + (size_t)b * STATE_ROW;
    float* opep = orow + PEP_OFF + n * N_PEPTIDE;

    float acc = 0.0f;
    #pragma unroll
    for (int p = 0; p < N_PEPTIDE; p++) {
        float c   = c0[p];
        float lap = cu[p] + cd[p] + cl[p] + cr[p] - 4.0f * c;
        float dpe = sP[p] * f - sR[p] * c + sD[p] * lap;
        opep[p] = c + dpe * DT_VAL;
        acc += c * sA[p];
    }

    float nd = fabsf(__ldg(ndecay));
    float d  = acc * pc2
             + g_syn[(size_t)b * N_NEURON + n]
             - nm * nd
             + __ldg(input_layer + n) * __ldg(u + b);

    orow[NEU_OFF + n] = (nm + d * DT_VAL) * abl;
    orow[n] = abl;
    if (n == 0) orow[N_NEURON] = pc2;
}

// ---------------------------------------------------------------------------
// Launch
// ---------------------------------------------------------------------------
extern "C" void kernel_launch(void* const* d_in, const int* in_sizes, int n_in,
                              void* d_out, int out_size)
{
    const float* u       = (const float*)d_in[0];
    const float* state   = (const float*)d_in[1];
    const float* noise   = (const float*)d_in[2];
    const float* D       = (const float*)d_in[3];
    const float* prod_r  = (const float*)d_in[4];
    const float* decay_r = (const float*)d_in[5];
    const float* action  = (const float*)d_in[6];
    const float* synapse = (const float*)d_in[7];
    const float* ndecay  = (const float*)d_in[8];
    const float* inlayer = (const float*)d_in[9];

    float* out       = (float*)d_out;
    float* firing    = out;                              // 2048*1024
    float* out_state = out + (size_t)BATCH * N_NEURON;   // 2048*18433

    float* syn_scratch;
    cudaGetSymbolAddress((void**)&syn_scratch, g_syn);

    cudaFuncSetAttribute(k_update, cudaFuncAttributeMaxDynamicSharedMemorySize, SMEM_BYTES);

    // 1) firing
    k_firing<<<(BATCH * N_NEURON) / 256, 256>>>(state, noise, firing);

    // 2) syn = firing @ synapse_matrix
    dim3 g2(N_NEURON / BN, BATCH / BM);
    k_sgemm<<<g2, 256>>>(firing, synapse, syn_scratch);

    // 3) peptide + neuron update, state_new assembly
    k_update<<<BATCH, N_NEURON, SMEM_BYTES>>>(state, u, firing, D, prod_r,
                                              decay_r, action, ndecay, inlayer,
                                              out_state);
}

// round 4
// speedup vs baseline: 2.6781x; 2.6781x over previous
#include <cuda_runtime.h>
#include <cuda_bf16.h>
#include <cstdint>

#define N_NEURON 1024
#define N_PEPTIDE 16
#define BATCH 2048
#define STATE_ROW 18433   // 1024 + 1 + 1024 + 16384
#define PEP_OFF 2049      // 1024 + 1 + 1024
#define NEU_OFF 1025
#define DT_VAL (1.0f / 120.0f)

// Scratch (8 MB f32 GEMM out + 4 MB bf16 A + 2 MB bf16 B)
__device__ float          g_syn[BATCH * N_NEURON];
__device__ __nv_bfloat16  g_A[BATCH * N_NEURON];
__device__ __nv_bfloat16  g_B[N_NEURON * N_NEURON];

__device__ __forceinline__ uint32_t s2u(const void* p) {
    return (uint32_t)__cvta_generic_to_shared(p);
}

// ---------------------------------------------------------------------------
// Kernel 0: synapse f32 -> bf16
// ---------------------------------------------------------------------------
__global__ void k_convB(const float* __restrict__ syn, __nv_bfloat16* __restrict__ out)
{
    int i = (blockIdx.x * blockDim.x + threadIdx.x) * 4;
    float4 v = *reinterpret_cast<const float4*>(syn + i);
    __nv_bfloat162* o = reinterpret_cast<__nv_bfloat162*>(out + i);
    o[0] = __floats2bfloat162_rn(v.x, v.y);
    o[1] = __floats2bfloat162_rn(v.z, v.w);
}

// ---------------------------------------------------------------------------
// Kernel 1: firing (f32 output + bf16 copy for GEMM), 2 elems/thread
// ---------------------------------------------------------------------------
__global__ void k_firing(const float* __restrict__ state,
                         const float* __restrict__ noise,
                         float* __restrict__ firing,
                         __nv_bfloat16* __restrict__ fbf)
{
    int idx = (blockIdx.x * blockDim.x + threadIdx.x) * 2;
    int b = idx >> 10;
    int n = idx & 1023;
    const float* srow = state + (size_t)b * STATE_ROW;
    float2 nz = *reinterpret_cast<const float2*>(noise + idx);
    float a0 = __ldg(srow + n),           a1 = __ldg(srow + n + 1);
    float v0 = __ldg(srow + NEU_OFF + n), v1 = __ldg(srow + NEU_OFF + n + 1);
    float f0 = -(fmaxf(v0, 0.0f) * a0 + 0.01f) * log1pf(-nz.x);
    float f1 = -(fmaxf(v1, 0.0f) * a1 + 0.01f) * log1pf(-nz.y);
    f0 = fminf(fmaxf(f0, 0.0f), 10.0f);
    f1 = fminf(fmaxf(f1, 0.0f), 10.0f);
    *reinterpret_cast<float2*>(firing + idx) = make_float2(f0, f1);
    *reinterpret_cast<__nv_bfloat162*>(fbf + idx) = __floats2bfloat162_rn(f0, f1);
}

// ---------------------------------------------------------------------------
// Kernel 2: bf16 tensor-core GEMM  C[2048,1024] = A[2048,1024] @ B[1024,1024]
// CTA 128x128, BK=32, 8 warps (2x4), warp tile 64x32, mma m16n8k16,
// cp.async double-buffered, ldmatrix (B via .trans).
// ---------------------------------------------------------------------------
#define SA_STRIDE 40    // halves per A smem row (80B; (m*5)%8 distinct -> no conflicts)
#define SB_STRIDE 136   // halves per B smem row (272B; (k*17)%8 distinct)
#define NKIT 32         // K / 32

__global__ __launch_bounds__(256, 1)
void k_gemm(const __nv_bfloat16* __restrict__ A,
            const __nv_bfloat16* __restrict__ B,
            float* __restrict__ C)
{
    __shared__ __align__(16) __nv_bfloat16 sA[2][128 * SA_STRIDE];
    __shared__ __align__(16) __nv_bfloat16 sB[2][32 * SB_STRIDE];

    const int tid = threadIdx.x, lane = tid & 31, wid = tid >> 5;
    const int bx = blockIdx.x, by = blockIdx.y;
    const int wm0 = (wid >> 2) * 64;
    const int wn0 = (wid & 3) * 32;

    const __nv_bfloat16* Abase = A + (size_t)(by * 128) * N_NEURON;
    const __nv_bfloat16* Bbase = B + bx * 128;

    float acc[4][4][4];
    #pragma unroll
    for (int mt = 0; mt < 4; mt++)
        #pragma unroll
        for (int nt = 0; nt < 4; nt++)
            #pragma unroll
            for (int r = 0; r < 4; r++) acc[mt][nt][r] = 0.0f;

    // chunk assignments (16B each): A = 512 chunks, B = 512 chunks
    auto load_tile = [&](int kt, int buf) {
        #pragma unroll
        for (int i = 0; i < 2; i++) {
            int c = tid + i * 256;
            int r = c >> 2, o = c & 3;                 // row 0..127, 16B-chunk 0..3
            uint32_t dst = s2u(&sA[buf][r * SA_STRIDE + o * 8]);
            const __nv_bfloat16* src = Abase + (size_t)r * N_NEURON + kt * 32 + o * 8;
            asm volatile("cp.async.cg.shared.global [%0],[%1],16;\n" :: "r"(dst), "l"(src) : "memory");
        }
        #pragma unroll
        for (int i = 0; i < 2; i++) {
            int c = tid + i * 256;
            int k = c >> 4, o = c & 15;                // k 0..31, 16B-chunk 0..15
            uint32_t dst = s2u(&sB[buf][k * SB_STRIDE + o * 8]);
            const __nv_bfloat16* src = Bbase + (size_t)(kt * 32 + k) * N_NEURON + o * 8;
            asm volatile("cp.async.cg.shared.global [%0],[%1],16;\n" :: "r"(dst), "l"(src) : "memory");
        }
    };

    auto compute = [&](int buf) {
        #pragma unroll
        for (int ks = 0; ks < 2; ks++) {
            const int k0 = ks * 16;
            uint32_t a[4][4];
            #pragma unroll
            for (int mt = 0; mt < 4; mt++) {
                uint32_t addr = s2u(&sA[buf][(wm0 + mt * 16 + (lane & 15)) * SA_STRIDE
                                             + k0 + (lane >> 4) * 8]);
                asm volatile("ldmatrix.sync.aligned.m8n8.x4.shared.b16 {%0,%1,%2,%3},[%4];\n"
                             : "=r"(a[mt][0]), "=r"(a[mt][1]), "=r"(a[mt][2]), "=r"(a[mt][3])
                             : "r"(addr));
            }
            uint32_t bfr[2][4];
            #pragma unroll
            for (int nt2 = 0; nt2 < 2; nt2++) {
                uint32_t addr = s2u(&sB[buf][(k0 + (lane & 15)) * SB_STRIDE
                                             + wn0 + nt2 * 16 + (lane >> 4) * 8]);
                asm volatile("ldmatrix.sync.aligned.m8n8.x4.trans.shared.b16 {%0,%1,%2,%3},[%4];\n"
                             : "=r"(bfr[nt2][0]), "=r"(bfr[nt2][1]), "=r"(bfr[nt2][2]), "=r"(bfr[nt2][3])
                             : "r"(addr));
            }
            #pragma unroll
            for (int mt = 0; mt < 4; mt++)
                #pragma unroll
                for (int nt = 0; nt < 4; nt++) {
                    uint32_t b0 = bfr[nt >> 1][(nt & 1) * 2];
                    uint32_t b1 = bfr[nt >> 1][(nt & 1) * 2 + 1];
                    asm volatile(
                        "mma.sync.aligned.m16n8k16.row.col.f32.bf16.bf16.f32 "
                        "{%0,%1,%2,%3},{%4,%5,%6,%7},{%8,%9},{%0,%1,%2,%3};\n"
                        : "+f"(acc[mt][nt][0]), "+f"(acc[mt][nt][1]),
                          "+f"(acc[mt][nt][2]), "+f"(acc[mt][nt][3])
                        : "r"(a[mt][0]), "r"(a[mt][1]), "r"(a[mt][2]), "r"(a[mt][3]),
                          "r"(b0), "r"(b1));
                }
        }
    };

    load_tile(0, 0);
    asm volatile("cp.async.commit_group;\n" ::: "memory");

    #pragma unroll 1
    for (int kt = 0; kt < NKIT; kt++) {
        if (kt < NKIT - 1) {
            load_tile(kt + 1, (kt + 1) & 1);
            asm volatile("cp.async.commit_group;\n" ::: "memory");
            asm volatile("cp.async.wait_group 1;\n" ::: "memory");
        } else {
            asm volatile("cp.async.wait_group 0;\n" ::: "memory");
        }
        __syncthreads();
        compute(kt & 1);
        __syncthreads();
    }

    // epilogue
    const int g = lane >> 2, t4 = lane & 3;
    #pragma unroll
    for (int mt = 0; mt < 4; mt++) {
        #pragma unroll
        for (int nt = 0; nt < 4; nt++) {
            int row = by * 128 + wm0 + mt * 16 + g;
            int col = bx * 128 + wn0 + nt * 8 + t4 * 2;
            float* p = C + (size_t)row * N_NEURON + col;
            *reinterpret_cast<float2*>(p) = make_float2(acc[mt][nt][0], acc[mt][nt][1]);
            *reinterpret_cast<float2*>(p + 8 * N_NEURON) = make_float2(acc[mt][nt][2], acc[mt][nt][3]);
        }
    }
}

// ---------------------------------------------------------------------------
// Kernel 3: peptide stencil + update + state assembly.
// One block per batch row, 1024 threads. SMEM rows padded to 17 words
// (stride 17 coprime with 32 -> conflict-free stencil LDS). New peptide
// values are written back into SMEM and copied out COALESCED.
// ---------------------------------------------------------------------------
#define PPAD 17
#define SMEM_BYTES (N_NEURON * PPAD * 4)

__global__ __launch_bounds__(1024, 1)
void k_update(const float* __restrict__ state,
              const float* __restrict__ u,
              const float* __restrict__ firing,
              const float* __restrict__ D,
              const float* __restrict__ prod_r,
              const float* __restrict__ decay_r,
              const float* __restrict__ action,
              const float* __restrict__ ndecay,
              const float* __restrict__ input_layer,
              float* __restrict__ out_state)
{
    extern __shared__ float sp[];             // 1024 * 17 floats
    __shared__ float sD[16], sP[16], sR[16], sA[16];

    int b = blockIdx.x;
    int n = threadIdx.x;

    if (n < 16) {
        sD[n] = fabsf(__ldg(D + n));
        sP[n] = fabsf(__ldg(prod_r + n));
        sR[n] = fabsf(__ldg(decay_r + n));
        sA[n] = __ldg(action + n);
    }

    const float* srow = state + (size_t)b * STATE_ROW;
    const float* pep  = srow + PEP_OFF;

    // Stage peptide grid into padded SMEM (coalesced global reads)
    #pragma unroll
    for (int e = n; e < N_NEURON * N_PEPTIDE; e += N_NEURON) {
        sp[(e >> 4) * PPAD + (e & 15)] = __ldg(pep + e);
    }
    __syncthreads();

    int i = n >> 5, j = n & 31;
    const float* c0 = sp + n * PPAD;
    const float* cu = sp + ((((i + 1)  & 31) << 5) | j) * PPAD;
    const float* cd = sp + ((((i + 31) & 31) << 5) | j) * PPAD;
    const float* cr = sp + (((i << 5) | ((j + 1)  & 31))) * PPAD;
    const float* cl = sp + (((i << 5) | ((j + 31) & 31))) * PPAD;

    float f   = __ldg(firing + (size_t)b * N_NEURON + n);
    float abl = __ldg(srow + n);
    float nm  = __ldg(srow + NEU_OFF + n) * abl;
    float pc2 = __ldg(srow + N_NEURON);

    float nv[N_PEPTIDE];
    float acc = 0.0f;
    #pragma unroll
    for (int p = 0; p < N_PEPTIDE; p++) {
        float c   = c0[p];
        float lap = cu[p] + cd[p] + cl[p] + cr[p] - 4.0f * c;
        float dpe = sP[p] * f - sR[p] * c + sD[p] * lap;
        nv[p] = c + dpe * DT_VAL;
        acc += c * sA[p];
    }

    float* orow = out_state + (size_t)b * STATE_ROW;

    float nd = fabsf(__ldg(ndecay));
    float d  = acc * pc2
             + g_syn[(size_t)b * N_NEURON + n]
             - nm * nd
             + __ldg(input_layer + n) * __ldg(u + b);

    orow[NEU_OFF + n] = (nm + d * DT_VAL) * abl;
    orow[n] = abl;
    if (n == 0) orow[N_NEURON] = pc2;

    // write new peptide values back to SMEM (stride 17 -> conflict-free)
    __syncthreads();
    float* w0 = sp + n * PPAD;
    #pragma unroll
    for (int p = 0; p < N_PEPTIDE; p++) w0[p] = nv[p];
    __syncthreads();

    // coalesced copy-out
    float* opep = orow + PEP_OFF;
    #pragma unroll
    for (int e = n; e < N_NEURON * N_PEPTIDE; e += N_NEURON) {
        opep[e] = sp[(e >> 4) * PPAD + (e & 15)];
    }
}

// ---------------------------------------------------------------------------
// Launch
// ---------------------------------------------------------------------------
extern "C" void kernel_launch(void* const* d_in, const int* in_sizes, int n_in,
                              void* d_out, int out_size)
{
    const float* u       = (const float*)d_in[0];
    const float* state   = (const float*)d_in[1];
    const float* noise   = (const float*)d_in[2];
    const float* D       = (const float*)d_in[3];
    const float* prod_r  = (const float*)d_in[4];
    const float* decay_r = (const float*)d_in[5];
    const float* action  = (const float*)d_in[6];
    const float* synapse = (const float*)d_in[7];
    const float* ndecay  = (const float*)d_in[8];
    const float* inlayer = (const float*)d_in[9];

    float* out       = (float*)d_out;
    float* firing    = out;                              // 2048*1024
    float* out_state = out + (size_t)BATCH * N_NEURON;   // 2048*18433

    float* syn_scratch;          cudaGetSymbolAddress((void**)&syn_scratch, g_syn);
    __nv_bfloat16* A_scratch;    cudaGetSymbolAddress((void**)&A_scratch, g_A);
    __nv_bfloat16* B_scratch;    cudaGetSymbolAddress((void**)&B_scratch, g_B);

    cudaFuncSetAttribute(k_update, cudaFuncAttributeMaxDynamicSharedMemorySize, SMEM_BYTES);

    // 0) synapse -> bf16
    k_convB<<<(N_NEURON * N_NEURON / 4) / 256, 256>>>(synapse, B_scratch);

    // 1) firing (f32 + bf16)
    k_firing<<<(BATCH * N_NEURON / 2) / 256, 256>>>(state, noise, firing, A_scratch);

    // 2) syn = firing @ synapse (bf16 tensor cores)
    dim3 g2(N_NEURON / 128, BATCH / 128);
    k_gemm<<<g2, 256>>>(A_scratch, B_scratch, syn_scratch);

    // 3) peptide + neuron update, state_new assembly
    k_update<<<BATCH, N_NEURON, SMEM_BYTES>>>(state, u, firing, D, prod_r,
                                              decay_r, action, ndecay, inlayer,
                                              out_state);
}

// round 6
// speedup vs baseline: 2.8756x; 1.0737x over previous
#include <cuda_runtime.h>
#include <cuda_bf16.h>
#include <cstdint>

#define N_NEURON 1024
#define N_PEPTIDE 16
#define BATCH 2048
#define STATE_ROW 18433   // 1024 + 1 + 1024 + 16384
#define PEP_OFF 2049      // 1024 + 1 + 1024
#define NEU_OFF 1025
#define DT_VAL (1.0f / 120.0f)

// Scratch (8 MB f32 GEMM out + 4 MB bf16 A + 2 MB bf16 B)
__device__ float          g_syn[BATCH * N_NEURON];
__device__ __nv_bfloat16  g_A[BATCH * N_NEURON];
__device__ __nv_bfloat16  g_B[N_NEURON * N_NEURON];

__device__ __forceinline__ uint32_t s2u(const void* p) {
    return (uint32_t)__cvta_generic_to_shared(p);
}

// ---------------------------------------------------------------------------
// Kernel 0: synapse f32 -> bf16
// ---------------------------------------------------------------------------
__global__ void k_convB(const float* __restrict__ syn, __nv_bfloat16* __restrict__ out)
{
    int i = (blockIdx.x * blockDim.x + threadIdx.x) * 4;
    float4 v = *reinterpret_cast<const float4*>(syn + i);
    __nv_bfloat162* o = reinterpret_cast<__nv_bfloat162*>(out + i);
    o[0] = __floats2bfloat162_rn(v.x, v.y);
    o[1] = __floats2bfloat162_rn(v.z, v.w);
}

// ---------------------------------------------------------------------------
// Kernel 1: firing (f32 output + bf16 copy for GEMM), 2 elems/thread
// ---------------------------------------------------------------------------
__global__ void k_firing(const float* __restrict__ state,
                         const float* __restrict__ noise,
                         float* __restrict__ firing,
                         __nv_bfloat16* __restrict__ fbf)
{
    int idx = (blockIdx.x * blockDim.x + threadIdx.x) * 2;
    int b = idx >> 10;
    int n = idx & 1023;
    const float* srow = state + (size_t)b * STATE_ROW;
    float2 nz = *reinterpret_cast<const float2*>(noise + idx);
    float a0 = __ldg(srow + n),           a1 = __ldg(srow + n + 1);
    float v0 = __ldg(srow + NEU_OFF + n), v1 = __ldg(srow + NEU_OFF + n + 1);
    float f0 = -(fmaxf(v0, 0.0f) * a0 + 0.01f) * log1pf(-nz.x);
    float f1 = -(fmaxf(v1, 0.0f) * a1 + 0.01f) * log1pf(-nz.y);
    f0 = fminf(fmaxf(f0, 0.0f), 10.0f);
    f1 = fminf(fmaxf(f1, 0.0f), 10.0f);
    *reinterpret_cast<float2*>(firing + idx) = make_float2(f0, f1);
    *reinterpret_cast<__nv_bfloat162*>(fbf + idx) = __floats2bfloat162_rn(f0, f1);
}

// ---------------------------------------------------------------------------
// Kernel 2: bf16 tensor-core GEMM  C[2048,1024] = A[2048,1024] @ B[1024,1024]
// (unchanged from R3 — CTA 128x128, BK=32, mma m16n8k16, cp.async x2)
// ---------------------------------------------------------------------------
#define SA_STRIDE 40
#define SB_STRIDE 136
#define NKIT 32

__global__ __launch_bounds__(256, 1)
void k_gemm(const __nv_bfloat16* __restrict__ A,
            const __nv_bfloat16* __restrict__ B,
            float* __restrict__ C)
{
    __shared__ __align__(16) __nv_bfloat16 sA[2][128 * SA_STRIDE];
    __shared__ __align__(16) __nv_bfloat16 sB[2][32 * SB_STRIDE];

    const int tid = threadIdx.x, lane = tid & 31, wid = tid >> 5;
    const int bx = blockIdx.x, by = blockIdx.y;
    const int wm0 = (wid >> 2) * 64;
    const int wn0 = (wid & 3) * 32;

    const __nv_bfloat16* Abase = A + (size_t)(by * 128) * N_NEURON;
    const __nv_bfloat16* Bbase = B + bx * 128;

    float acc[4][4][4];
    #pragma unroll
    for (int mt = 0; mt < 4; mt++)
        #pragma unroll
        for (int nt = 0; nt < 4; nt++)
            #pragma unroll
            for (int r = 0; r < 4; r++) acc[mt][nt][r] = 0.0f;

    auto load_tile = [&](int kt, int buf) {
        #pragma unroll
        for (int i = 0; i < 2; i++) {
            int c = tid + i * 256;
            int r = c >> 2, o = c & 3;
            uint32_t dst = s2u(&sA[buf][r * SA_STRIDE + o * 8]);
            const __nv_bfloat16* src = Abase + (size_t)r * N_NEURON + kt * 32 + o * 8;
            asm volatile("cp.async.cg.shared.global [%0],[%1],16;\n" :: "r"(dst), "l"(src) : "memory");
        }
        #pragma unroll
        for (int i = 0; i < 2; i++) {
            int c = tid + i * 256;
            int k = c >> 4, o = c & 15;
            uint32_t dst = s2u(&sB[buf][k * SB_STRIDE + o * 8]);
            const __nv_bfloat16* src = Bbase + (size_t)(kt * 32 + k) * N_NEURON + o * 8;
            asm volatile("cp.async.cg.shared.global [%0],[%1],16;\n" :: "r"(dst), "l"(src) : "memory");
        }
    };

    auto compute = [&](int buf) {
        #pragma unroll
        for (int ks = 0; ks < 2; ks++) {
            const int k0 = ks * 16;
            uint32_t a[4][4];
            #pragma unroll
            for (int mt = 0; mt < 4; mt++) {
                uint32_t addr = s2u(&sA[buf][(wm0 + mt * 16 + (lane & 15)) * SA_STRIDE
                                             + k0 + (lane >> 4) * 8]);
                asm volatile("ldmatrix.sync.aligned.m8n8.x4.shared.b16 {%0,%1,%2,%3},[%4];\n"
                             : "=r"(a[mt][0]), "=r"(a[mt][1]), "=r"(a[mt][2]), "=r"(a[mt][3])
                             : "r"(addr));
            }
            uint32_t bfr[2][4];
            #pragma unroll
            for (int nt2 = 0; nt2 < 2; nt2++) {
                uint32_t addr = s2u(&sB[buf][(k0 + (lane & 15)) * SB_STRIDE
                                             + wn0 + nt2 * 16 + (lane >> 4) * 8]);
                asm volatile("ldmatrix.sync.aligned.m8n8.x4.trans.shared.b16 {%0,%1,%2,%3},[%4];\n"
                             : "=r"(bfr[nt2][0]), "=r"(bfr[nt2][1]), "=r"(bfr[nt2][2]), "=r"(bfr[nt2][3])
                             : "r"(addr));
            }
            #pragma unroll
            for (int mt = 0; mt < 4; mt++)
                #pragma unroll
                for (int nt = 0; nt < 4; nt++) {
                    uint32_t b0 = bfr[nt >> 1][(nt & 1) * 2];
                    uint32_t b1 = bfr[nt >> 1][(nt & 1) * 2 + 1];
                    asm volatile(
                        "mma.sync.aligned.m16n8k16.row.col.f32.bf16.bf16.f32 "
                        "{%0,%1,%2,%3},{%4,%5,%6,%7},{%8,%9},{%0,%1,%2,%3};\n"
                        : "+f"(acc[mt][nt][0]), "+f"(acc[mt][nt][1]),
                          "+f"(acc[mt][nt][2]), "+f"(acc[mt][nt][3])
                        : "r"(a[mt][0]), "r"(a[mt][1]), "r"(a[mt][2]), "r"(a[mt][3]),
                          "r"(b0), "r"(b1));
                }
        }
    };

    load_tile(0, 0);
    asm volatile("cp.async.commit_group;\n" ::: "memory");

    #pragma unroll 1
    for (int kt = 0; kt < NKIT; kt++) {
        if (kt < NKIT - 1) {
            load_tile(kt + 1, (kt + 1) & 1);
            asm volatile("cp.async.commit_group;\n" ::: "memory");
            asm volatile("cp.async.wait_group 1;\n" ::: "memory");
        } else {
            asm volatile("cp.async.wait_group 0;\n" ::: "memory");
        }
        __syncthreads();
        compute(kt & 1);
        __syncthreads();
    }

    const int g = lane >> 2, t4 = lane & 3;
    #pragma unroll
    for (int mt = 0; mt < 4; mt++) {
        #pragma unroll
        for (int nt = 0; nt < 4; nt++) {
            int row = by * 128 + wm0 + mt * 16 + g;
            int col = bx * 128 + wn0 + nt * 8 + t4 * 2;
            float* p = C + (size_t)row * N_NEURON + col;
            *reinterpret_cast<float2*>(p) = make_float2(acc[mt][nt][0], acc[mt][nt][1]);
            *reinterpret_cast<float2*>(p + 8 * N_NEURON) = make_float2(acc[mt][nt][2], acc[mt][nt][3]);
        }
    }
}

// ---------------------------------------------------------------------------
// Kernel 3 (REWRITTEN): peptide stencil + update + state assembly.
// One block per batch row, 1024 threads, 2 CTAs/SM.
// DENSE smem layout: element index e = r*16+c directly; thread n outputs
// elements e = n + 1024p -> center/neighbor LDS conflict-free, STG coalesced.
// acc = sum(pep*action) computed in the staging loop via 16-lane shfl reduce
// (warp's 32 coalesced staged values = exactly 2 peptide rows).
// ---------------------------------------------------------------------------
#define SMEM_BYTES ((N_NEURON * N_PEPTIDE + 2 * N_NEURON) * 4)

__global__ __launch_bounds__(1024, 2)
void k_update(const float* __restrict__ state,
              const float* __restrict__ u,
              const float* __restrict__ firing,
              const float* __restrict__ D,
              const float* __restrict__ prod_r,
              const float* __restrict__ decay_r,
              const float* __restrict__ action,
              const float* __restrict__ ndecay,
              const float* __restrict__ input_layer,
              float* __restrict__ out_state)
{
    extern __shared__ float sp[];                 // [16384] dense peptide
    float* sacc = sp + N_NEURON * N_PEPTIDE;      // [1024]
    float* sf   = sacc + N_NEURON;                // [1024]
    __shared__ float sD[16], sP[16], sR[16], sA[16];

    const int b = blockIdx.x;
    const int n = threadIdx.x;

    if (n < 16) {
        sD[n] = fabsf(__ldg(D + n));
        sP[n] = fabsf(__ldg(prod_r + n));
        sR[n] = fabsf(__ldg(decay_r + n));
        sA[n] = __ldg(action + n);
    }
    __syncthreads();   // sA must be valid before the staging reduction

    const float* srow = state + (size_t)b * STATE_ROW;
    const float* pep  = srow + PEP_OFF;
    const int c_lane = n & 15;

    // firing stage (coalesced)
    float fmine = __ldg(firing + (size_t)b * N_NEURON + n);
    sf[n] = fmine;

    // Stage peptide (coalesced) + fused acc reduction.
    // Warp covers 32 consecutive e -> two peptide rows; 16-lane xor-reduce.
    #pragma unroll
    for (int p = 0; p < N_PEPTIDE; p++) {
        int e = n + p * N_NEURON;
        float v = __ldg(pep + e);
        sp[e] = v;
        float w = v * sA[c_lane];
        w += __shfl_xor_sync(0xffffffffu, w, 1);
        w += __shfl_xor_sync(0xffffffffu, w, 2);
        w += __shfl_xor_sync(0xffffffffu, w, 4);
        w += __shfl_xor_sync(0xffffffffu, w, 8);
        if (c_lane == 0) sacc[e >> 4] = w;
    }
    __syncthreads();

    // Neuron update (reads sacc conflict-free)
    {
        float abl = __ldg(srow + n);
        float nm  = __ldg(srow + NEU_OFF + n) * abl;
        float pc2 = __ldg(srow + N_NEURON);
        float nd  = fabsf(__ldg(ndecay));
        float d   = sacc[n] * pc2
                  + g_syn[(size_t)b * N_NEURON + n]
                  - nm * nd
                  + __ldg(input_layer + n) * __ldg(u + b);
        float* orow = out_state + (size_t)b * STATE_ROW;
        orow[NEU_OFF + n] = (nm + d * DT_VAL) * abl;
        orow[n] = abl;
        if (n == 0) orow[N_NEURON] = pc2;
    }

    // Peptide outputs: thread n -> elements e = n + 1024p, coalesced STG.
    float* opep = out_state + (size_t)b * STATE_ROW + PEP_OFF;
    #pragma unroll 4
    for (int p = 0; p < N_PEPTIDE; p++) {
        int e = n + p * N_NEURON;
        int r = e >> 4, c = e & 15;
        int i = r >> 5, j = r & 31;
        float cc = sp[e];
        float up = sp[(((((i + 1)  & 31) << 5) | j) << 4) + c];
        float dn = sp[(((((i + 31) & 31) << 5) | j) << 4) + c];
        float rt = sp[((( i << 5) | ((j + 1)  & 31)) << 4) + c];
        float lf = sp[((( i << 5) | ((j + 31) & 31)) << 4) + c];
        float lap = up + dn + rt + lf - 4.0f * cc;
        float dpe = sP[c] * sf[r] - sR[c] * cc + sD[c] * lap;
        opep[e] = cc + dpe * DT_VAL;
    }
}

// ---------------------------------------------------------------------------
// Launch
// ---------------------------------------------------------------------------
extern "C" void kernel_launch(void* const* d_in, const int* in_sizes, int n_in,
                              void* d_out, int out_size)
{
    const float* u       = (const float*)d_in[0];
    const float* state   = (const float*)d_in[1];
    const float* noise   = (const float*)d_in[2];
    const float* D       = (const float*)d_in[3];
    const float* prod_r  = (const float*)d_in[4];
    const float* decay_r = (const float*)d_in[5];
    const float* action  = (const float*)d_in[6];
    const float* synapse = (const float*)d_in[7];
    const float* ndecay  = (const float*)d_in[8];
    const float* inlayer = (const float*)d_in[9];

    float* out       = (float*)d_out;
    float* firing    = out;                              // 2048*1024
    float* out_state = out + (size_t)BATCH * N_NEURON;   // 2048*18433

    float* syn_scratch;          cudaGetSymbolAddress((void**)&syn_scratch, g_syn);
    __nv_bfloat16* A_scratch;    cudaGetSymbolAddress((void**)&A_scratch, g_A);
    __nv_bfloat16* B_scratch;    cudaGetSymbolAddress((void**)&B_scratch, g_B);

    cudaFuncSetAttribute(k_update, cudaFuncAttributeMaxDynamicSharedMemorySize, SMEM_BYTES);

    // 0) synapse -> bf16
    k_convB<<<(N_NEURON * N_NEURON / 4) / 256, 256>>>(synapse, B_scratch);

    // 1) firing (f32 + bf16)
    k_firing<<<(BATCH * N_NEURON / 2) / 256, 256>>>(state, noise, firing, A_scratch);

    // 2) syn = firing @ synapse (bf16 tensor cores)
    dim3 g2(N_NEURON / 128, BATCH / 128);
    k_gemm<<<g2, 256>>>(A_scratch, B_scratch, syn_scratch);

    // 3) peptide + neuron update, state_new assembly
    k_update<<<BATCH, N_NEURON, SMEM_BYTES>>>(state, u, firing, D, prod_r,
                                              decay_r, action, ndecay, inlayer,
                                              out_state);
}